// round 3
// baseline (speedup 1.0000x reference)
#include <cuda_runtime.h>

#define NC 5
#define TPB 256

__device__ __forceinline__ float fast_ex2(float x) {
    float y; asm("ex2.approx.f32 %0, %1;" : "=f"(y) : "f"(x)); return y;
}
__device__ __forceinline__ float fast_lg2(float x) {
    float y; asm("lg2.approx.f32 %0, %1;" : "=f"(y) : "f"(x)); return y;
}
__device__ __forceinline__ float fast_rcp(float x) {
    float y; asm("rcp.approx.f32 %0, %1;" : "=f"(y) : "f"(x)); return y;
}

// Constraint in log2 domain, p(t) = softmax(t * ln q), Z(t) = sum q_j^t:
//   h(t)   = t*mu(t) - log2 Z(t) + C2,  C2 = (ln5 - eps)/ln2,  h increasing
//   h'(t)  = t * v(t) * ln2                (v = Var_p[log2 q])
//   h''(t) = ln2 * v + t * ln2^2 * m3      (m3 = third central moment of log2 q)
// Feasible (lam = 0) iff h(1) <= 0.
#define C2CONST 2.1776498f    // (ln5 - 0.1)/ln2
#define LN2F    0.6931471806f

__global__ void __launch_bounds__(TPB) kl_proj_kernel(
    const float* __restrict__ x,
    const float* __restrict__ W,
    const float* __restrict__ b,
    float* __restrict__ out,
    int n)
{
    __shared__ float sW[NC * NC];
    __shared__ float sb[NC];
    if (threadIdx.x < NC * NC) sW[threadIdx.x] = W[threadIdx.x];
    if (threadIdx.x < NC)      sb[threadIdx.x] = b[threadIdx.x];
    __syncthreads();

    int row = blockIdx.x * blockDim.x + threadIdx.x;
    if (row >= n) return;
    unsigned mask = __activemask();

    // q = x @ W^T + b; q in [0.1, 3.1] by construction -> no max-shift anywhere.
    float xv[NC];
    #pragma unroll
    for (int k = 0; k < NC; k++) xv[k] = x[row * NC + k];

    float qv[NC], L[NC];
    #pragma unroll
    for (int j = 0; j < NC; j++) {
        float q = sb[j];
        #pragma unroll
        for (int k = 0; k < NC; k++) q = fmaf(xv[k], sW[j * NC + k], q);
        qv[j] = q;
        L[j]  = fast_lg2(q);
    }

    // ---- Feasibility at t = 1, using raw q (no ex2 needed) ----
    float S1 = 0.f, A1 = 0.f;
    #pragma unroll
    for (int j = 0; j < NC; j++) { S1 += qv[j]; A1 = fmaf(qv[j], L[j], A1); }
    float h1 = A1 * fast_rcp(S1) - fast_lg2(S1) + C2CONST;
    bool feas = (h1 <= 0.f);

    float t = 1.f;
    if (!__all_sync(mask, feas)) {
        // Init: KL ~ t^2 * Var_u(ln q)/2  =>  t0 = sqrt(2 eps / Var_u)
        float su = 0.f, sq = 0.f;
        #pragma unroll
        for (int j = 0; j < NC; j++) { su += L[j]; sq = fmaf(L[j], L[j], sq); }
        float muu = su * 0.2f;
        float vu  = fmaf(sq, 0.2f, -muu * muu) * 0.48045302f;  // * ln2^2
        float t0  = sqrtf(0.2f * fast_rcp(fmaxf(vu, 1e-9f)));
        t0 = fminf(0.95f, fmaxf(t0, 1e-4f));

        float lo = 0.f, hi = 1.f;
        float tc = t0;
        // 3 safeguarded Halley iterations (cubic convergence), fully unrolled.
        #pragma unroll
        for (int it = 0; it < 3; ++it) {
            float S = 0.f, A = 0.f, B = 0.f, C = 0.f;
            #pragma unroll
            for (int j = 0; j < NC; j++) {
                float e  = fast_ex2(tc * L[j]);
                float el = e * L[j];
                S += e;
                A += el;
                B = fmaf(el, L[j], B);
                C = fmaf(el * L[j], L[j], C);
            }
            float r   = fast_rcp(S);
            float mu  = A * r;
            float m2  = B * r;                  // E[L^2]
            float v   = m2 - mu * mu;           // Var
            float m3  = fmaf(C, r, fmaf(-3.f * mu, m2, 2.f * mu * mu * mu));
            float h   = fmaf(tc, mu, C2CONST - fast_lg2(S));
            float hp  = tc * v * LN2F;
            float hpp = fmaf(tc * LN2F, m3, v) * LN2F;

            bool pos = (h > 0.f);
            hi = pos ? tc : hi;
            lo = pos ? lo : tc;

            // Halley: tn = tc - 2 h h' / (2 h'^2 - h h'')
            float den = fmaf(-h, hpp, 2.f * hp * hp);
            float tn  = fmaf(-2.f * h * hp, fast_rcp(den), tc);
            bool ok = (tn > lo) && (tn < hi);   // false also on NaN / bad den
            tc = ok ? tn : 0.5f * (lo + hi);
        }
        t = feas ? 1.f : tc;
    }

    // Final p = softmax(t * log2 q) (exponents bounded; no shift), NR-refined rcp.
    float e[NC], S = 0.f;
    #pragma unroll
    for (int j = 0; j < NC; j++) { e[j] = fast_ex2(t * L[j]); S += e[j]; }
    float r = fast_rcp(S);
    r = r * (2.f - S * r);
    #pragma unroll
    for (int j = 0; j < NC; j++) out[row * NC + j] = e[j] * r;
}

extern "C" void kernel_launch(void* const* d_in, const int* in_sizes, int n_in,
                              void* d_out, int out_size) {
    const float* x = (const float*)d_in[0];
    const float* W = (const float*)d_in[1];
    const float* b = (const float*)d_in[2];
    float* out = (float*)d_out;
    int n = in_sizes[0] / NC;
    int blocks = (n + TPB - 1) / TPB;
    kl_proj_kernel<<<blocks, TPB>>>(x, W, b, out, n);
}

// round 4
// speedup vs baseline: 1.4467x; 1.4467x over previous
#include <cuda_runtime.h>

#define NC 5
#define TPB 256

__device__ __forceinline__ float fast_ex2(float x) {
    float y; asm("ex2.approx.f32 %0, %1;" : "=f"(y) : "f"(x)); return y;
}
__device__ __forceinline__ float fast_lg2(float x) {
    float y; asm("lg2.approx.f32 %0, %1;" : "=f"(y) : "f"(x)); return y;
}
__device__ __forceinline__ float fast_rcp(float x) {
    float y; asm("rcp.approx.f32 %0, %1;" : "=f"(y) : "f"(x)); return y;
}

// Constraint in log2 domain:
//   h(t)  = t*mu(t) - log2 Z(t) + C2,   C2 = (ln5 - eps)/ln2,  h increasing
//   h'(t) = ln2 * t * Var_p(log2 q)
// p(t) = softmax(t * ln q). Feasible (lam=0) iff h(1) <= 0.
#define C2CONST 2.1776498f   // (ln5 - 0.1)/ln2
#define LN2SQ   0.48045302f  // ln2^2

__global__ void __launch_bounds__(TPB) kl_proj_kernel(
    const float* __restrict__ x,
    const float* __restrict__ W,
    const float* __restrict__ b,
    float* __restrict__ out,
    int n)
{
    __shared__ float sW[NC * NC];
    __shared__ float sb[NC];
    if (threadIdx.x < NC * NC) sW[threadIdx.x] = W[threadIdx.x];
    if (threadIdx.x < NC)      sb[threadIdx.x] = b[threadIdx.x];
    __syncthreads();

    int row = blockIdx.x * blockDim.x + threadIdx.x;
    if (row >= n) return;
    unsigned mask = __activemask();

    // q = x @ W^T + b; q in [0.1, 3.1] by construction -> no max-shift anywhere.
    float xv[NC];
    #pragma unroll
    for (int k = 0; k < NC; k++) xv[k] = x[row * NC + k];

    // Linear + log, with feasibility accumulators fused in (q is transient).
    float L[NC];
    float S1 = 0.f, A1 = 0.f;
    #pragma unroll
    for (int j = 0; j < NC; j++) {
        float q = sb[j];
        #pragma unroll
        for (int k = 0; k < NC; k++) q = fmaf(xv[k], sW[j * NC + k], q);
        float lj = fast_lg2(q);
        L[j] = lj;
        S1 += q;
        A1 = fmaf(q, lj, A1);
    }

    // Feasibility at t = 1: h(1) = E_p[log2 q] - log2(sum q) + C2
    float h1 = A1 * fast_rcp(S1) - fast_lg2(S1) + C2CONST;
    bool feas = (h1 <= 0.f);

    float t = 1.f;
    if (!__all_sync(mask, feas)) {
        // Init: KL ~ t^2 * Var_u(ln q)/2  =>  t0 = sqrt(2 eps / Var_u)
        float su = 0.f, sq = 0.f;
        #pragma unroll
        for (int j = 0; j < NC; j++) { su += L[j]; sq = fmaf(L[j], L[j], sq); }
        float muu = su * 0.2f;
        float vu  = fmaf(sq, 0.2f, -muu * muu) * LN2SQ;
        float t0  = sqrtf(0.2f * fast_rcp(fmaxf(vu, 1e-9f)));  // 2*eps = 0.2
        t0 = fminf(0.95f, fmaxf(t0, 1e-4f));

        float lo = 0.f, hi = 1.f;
        float tc = t0;
        // 4 safeguarded Newton iterations, fully unrolled (no votes, no branches).
        #pragma unroll
        for (int it = 0; it < 4; ++it) {
            float S = 0.f, A = 0.f, B = 0.f;
            #pragma unroll
            for (int j = 0; j < NC; j++) {
                float e  = fast_ex2(tc * L[j]);
                float el = e * L[j];
                S += e;
                A = fmaf(e,  L[j], A);
                B = fmaf(el, L[j], B);
            }
            float r  = fast_rcp(S);
            float mu = A * r;
            float v  = fmaf(B, r, -(mu * mu));
            float h  = fmaf(tc, mu, C2CONST - fast_lg2(S));
            float hp = tc * v;   // h' / ln2; fold ln2 into the step via h scaling

            bool pos = (h > 0.f);
            hi = pos ? tc : hi;
            lo = pos ? lo : tc;
            // Newton step: tn = tc - h / (ln2 * tc * v) = tc - (h/ln2) / hp
            float tn = fmaf(-h * 1.44269504f, fast_rcp(hp), tc);
            bool ok = (tn > lo) && (tn < hi);   // false also on NaN
            tc = ok ? tn : 0.5f * (lo + hi);
        }
        t = feas ? 1.f : tc;
    }

    // Final p = softmax(t * log2 q) (exponents bounded; no shift), NR-refined rcp.
    float e[NC], S = 0.f;
    #pragma unroll
    for (int j = 0; j < NC; j++) { e[j] = fast_ex2(t * L[j]); S += e[j]; }
    float r = fast_rcp(S);
    r = r * (2.f - S * r);
    #pragma unroll
    for (int j = 0; j < NC; j++) out[row * NC + j] = e[j] * r;
}

extern "C" void kernel_launch(void* const* d_in, const int* in_sizes, int n_in,
                              void* d_out, int out_size) {
    const float* x = (const float*)d_in[0];
    const float* W = (const float*)d_in[1];
    const float* b = (const float*)d_in[2];
    float* out = (float*)d_out;
    int n = in_sizes[0] / NC;
    int blocks = (n + TPB - 1) / TPB;
    kl_proj_kernel<<<blocks, TPB>>>(x, W, b, out, n);
}